// round 4
// baseline (speedup 1.0000x reference)
#include <cuda_runtime.h>
#include <math.h>

// NeuralODE on GB300, round 4.
// ode_kernel: warp owns NB=4 batch elements -> 1024 warp-tasks = ONE wave at
//   8 warps/SM (vs 2 waves before), and 4-way per-warp ILP hides the
//   layer-boundary latency chains. Weights register-resident K-packed u64
//   (fma.rn.f32x2); activations via per-warp smem broadcast (LDS.128).
//   launch_bounds(128,2) pins 2 CTAs/SM.
// dec_kernel: unchanged from round 3.

namespace {

constexpr int kB = 4096;
constexpr int kT = 101;
constexpr int kH = 64;
constexpr int NSTEPS = kT - 1;

constexpr int NB = 4;                       // elements per warp
constexpr int WARPS = 4;                    // warps per block
constexpr int THREADS = WARPS * 32;
constexpr int ELEMS_PER_BLOCK = WARPS * NB; // 16
constexpr int GRID = kB / ELEMS_PER_BLOCK;  // 256 -> one wave at 2 CTA/SM

constexpr float A21 = 0.161f;
constexpr float A31 = -0.008480655492356989f, A32 = 0.335480655492357f;
constexpr float A41 = 2.8971530571054935f, A42 = -6.359448489975075f, A43 = 4.3622954328695815f;
constexpr float A51 = 5.325864828439257f, A52 = -11.748883564062828f;
constexpr float A53 = 7.4955393428898365f, A54 = -0.09249506636175525f;
constexpr float A61 = 5.86145544294642f, A62 = -12.92096931784711f;
constexpr float A63 = 8.159367898576159f, A64 = -0.071584973281401f, A65 = -0.028269050394068383f;
constexpr float B1c = 0.09646076681806523f, B2c = 0.01f, B3c = 0.4798896504144996f;
constexpr float B4c = 1.379008574103742f, B5c = -3.290069515436081f, B6c = 2.324710524099774f;

using u64 = unsigned long long;

__device__ __forceinline__ u64 pk(float x, float y) {
    u64 r; asm("mov.b64 %0, {%1,%2};" : "=l"(r) : "f"(x), "f"(y)); return r;
}
__device__ __forceinline__ u64 fma2(u64 a, u64 b, u64 c) {
    u64 d; asm("fma.rn.f32x2 %0, %1, %2, %3;" : "=l"(d) : "l"(a), "l"(b), "l"(c)); return d;
}
__device__ __forceinline__ u64 add2(u64 a, u64 b) {
    u64 d; asm("add.rn.f32x2 %0, %1, %2;" : "=l"(d) : "l"(a), "l"(b)); return d;
}
__device__ __forceinline__ float hsum2(u64 a, u64 b) {
    u64 s = add2(a, b);
    float x, y;
    asm("mov.b64 {%0,%1}, %2;" : "=f"(x), "=f"(y) : "l"(s));
    return x + y;
}
__device__ __forceinline__ float tanh_f(float x) {
    // tanh(x) = 1 - 2/(e^{2x}+1). Correct limits at +-inf. ~1e-7 rel err.
    float ex;
    asm("ex2.approx.f32 %0, %1;" : "=f"(ex) : "f"(x * 2.885390081777927f));
    float r;
    asm("rcp.approx.f32 %0, %1;" : "=f"(r) : "f"(ex + 1.0f));
    return fmaf(-2.0f, r, 1.0f);
}

__global__ void __launch_bounds__(THREADS, 2)
ode_kernel(
    const float* __restrict__ ts, const float* __restrict__ y0,
    const float* __restrict__ encW, const float* __restrict__ encb,
    const float* __restrict__ W1g, const float* __restrict__ b1g,
    const float* __restrict__ W2g, const float* __restrict__ b2g,
    const float* __restrict__ W3g, const float* __restrict__ b3g,
    float* __restrict__ zs)
{
    // per warp: su[4][64], sh1[4][32], sh2[4][32] = 512 floats
    __shared__ __align__(16) float sm[WARPS * 512];
    const int lane = threadIdx.x & 31;
    const int wid = threadIdx.x >> 5;
    float* base = sm + wid * 512;
    // su[e] = base + e*64 ; sh1[e] = base + 256 + e*32 ; sh2[e] = base + 384 + e*32
    const int b0 = blockIdx.x * ELEMS_PER_BLOCK + wid * NB;

    // ---- register-resident MLP weights, K-packed ----
    u64 w1p[32];   // W1[lane][0..63]
    u64 w2p[16];   // W2[lane][0..31]
    u64 w3a[16];   // W3[2*lane][0..31]
    u64 w3b[16];   // W3[2*lane+1][0..31]
    {
        const ulonglong2* v1 = reinterpret_cast<const ulonglong2*>(W1g + lane * 64);
#pragma unroll
        for (int i = 0; i < 16; i++) { ulonglong2 v = v1[i]; w1p[2*i] = v.x; w1p[2*i+1] = v.y; }
        const ulonglong2* v2 = reinterpret_cast<const ulonglong2*>(W2g + lane * 32);
#pragma unroll
        for (int i = 0; i < 8; i++) { ulonglong2 v = v2[i]; w2p[2*i] = v.x; w2p[2*i+1] = v.y; }
        const ulonglong2* v3a = reinterpret_cast<const ulonglong2*>(W3g + (2*lane) * 32);
        const ulonglong2* v3b = reinterpret_cast<const ulonglong2*>(W3g + (2*lane+1) * 32);
#pragma unroll
        for (int i = 0; i < 8; i++) {
            ulonglong2 a = v3a[i], b = v3b[i];
            w3a[2*i] = a.x; w3a[2*i+1] = a.y;
            w3b[2*i] = b.x; w3b[2*i+1] = b.y;
        }
    }
    const float b1r = b1g[lane];
    const float b2r = b2g[lane];
    const float2 b3p = *reinterpret_cast<const float2*>(b3g + 2 * lane);
    const float dt = (ts[kT - 1] - ts[0]) / (float)NSTEPS;

    // ---- encoder for all 4 elements ----
    float z0[NB], z1[NB];
    {
#pragma unroll
        for (int e = 0; e < NB; e++)
            reinterpret_cast<float2*>(base + e * 64)[lane] =
                *reinterpret_cast<const float2*>(y0 + (size_t)(b0 + e) * 64 + 2 * lane);
        __syncwarp();
        const ulonglong2* Ea = reinterpret_cast<const ulonglong2*>(encW + (2*lane) * 64);
        const ulonglong2* Eb = reinterpret_cast<const ulonglong2*>(encW + (2*lane+1) * 64);
        const float2 eb = *reinterpret_cast<const float2*>(encb + 2 * lane);
#pragma unroll
        for (int e = 0; e < NB; e++) {
            const ulonglong2* u = reinterpret_cast<const ulonglong2*>(base + e * 64);
            u64 a0 = 0, a1 = 0, c0 = 0, c1 = 0;
#pragma unroll
            for (int kc = 0; kc < 16; kc++) {
                ulonglong2 wA = Ea[kc], wB = Eb[kc];
                ulonglong2 v = u[kc];
                a0 = fma2(v.x, wA.x, a0); a1 = fma2(v.y, wA.y, a1);
                c0 = fma2(v.x, wB.x, c0); c1 = fma2(v.y, wB.y, c1);
            }
            z0[e] = hsum2(a0, a1) + eb.x;
            z1[e] = hsum2(c0, c1) + eb.y;
        }
        __syncwarp();
    }

    // MLP field eval for all 4 elements; inputs already in su[e].
    auto mlp4 = [&](float (&ol)[NB], float (&oh)[NB]) {
        // layer 1: 64 -> 32, tanh
        {
            u64 a0[NB], a1[NB];
#pragma unroll
            for (int e = 0; e < NB; e++) { a0[e] = pk(b1r, 0.f); a1[e] = 0; }
#pragma unroll
            for (int kc = 0; kc < 16; kc++) {
#pragma unroll
                for (int e = 0; e < NB; e++) {
                    ulonglong2 v = reinterpret_cast<const ulonglong2*>(base + e * 64)[kc];
                    a0[e] = fma2(v.x, w1p[2*kc], a0[e]);
                    a1[e] = fma2(v.y, w1p[2*kc+1], a1[e]);
                }
            }
#pragma unroll
            for (int e = 0; e < NB; e++)
                base[256 + e * 32 + lane] = tanh_f(hsum2(a0[e], a1[e]));
            __syncwarp();
        }
        // layer 2: 32 -> 32, tanh
        {
            u64 c0[NB], c1[NB];
#pragma unroll
            for (int e = 0; e < NB; e++) { c0[e] = pk(b2r, 0.f); c1[e] = 0; }
#pragma unroll
            for (int kc = 0; kc < 8; kc++) {
#pragma unroll
                for (int e = 0; e < NB; e++) {
                    ulonglong2 v = reinterpret_cast<const ulonglong2*>(base + 256 + e * 32)[kc];
                    c0[e] = fma2(v.x, w2p[2*kc], c0[e]);
                    c1[e] = fma2(v.y, w2p[2*kc+1], c1[e]);
                }
            }
#pragma unroll
            for (int e = 0; e < NB; e++)
                base[384 + e * 32 + lane] = tanh_f(hsum2(c0[e], c1[e]));
            __syncwarp();
        }
        // layer 3: 32 -> 64 (lane outputs comps 2*lane, 2*lane+1)
        {
#pragma unroll
            for (int e = 0; e < NB; e++) {
                u64 d0 = pk(b3p.x, 0.f), d1 = 0, g0 = pk(b3p.y, 0.f), g1 = 0;
#pragma unroll
                for (int kc = 0; kc < 8; kc++) {
                    ulonglong2 v = reinterpret_cast<const ulonglong2*>(base + 384 + e * 32)[kc];
                    d0 = fma2(v.x, w3a[2*kc], d0);
                    d1 = fma2(v.y, w3a[2*kc+1], d1);
                    g0 = fma2(v.x, w3b[2*kc], g0);
                    g1 = fma2(v.y, w3b[2*kc+1], g1);
                }
                ol[e] = hsum2(d0, d1);
                oh[e] = hsum2(g0, g1);
            }
        }
    };

    float k1l[NB], k1h[NB], k2l[NB], k2h[NB], k3l[NB], k3h[NB];
    float k4l[NB], k4h[NB], k5l[NB], k5h[NB], k6l[NB], k6h[NB];

#pragma unroll 1
    for (int t = 0; t < NSTEPS; t++) {
        // store zs[b, t, :] and publish u = z
#pragma unroll
        for (int e = 0; e < NB; e++) {
            reinterpret_cast<float2*>(zs + ((size_t)(b0 + e) * kT + t) * kH)[lane] =
                make_float2(z0[e], z1[e]);
            reinterpret_cast<float2*>(base + e * 64)[lane] = make_float2(z0[e], z1[e]);
        }
        __syncwarp();
        mlp4(k1l, k1h);

#pragma unroll
        for (int e = 0; e < NB; e++)
            reinterpret_cast<float2*>(base + e * 64)[lane] =
                make_float2(fmaf(dt, A21 * k1l[e], z0[e]), fmaf(dt, A21 * k1h[e], z1[e]));
        __syncwarp();
        mlp4(k2l, k2h);

#pragma unroll
        for (int e = 0; e < NB; e++) {
            float al = fmaf(A32, k2l[e], A31 * k1l[e]);
            float ah = fmaf(A32, k2h[e], A31 * k1h[e]);
            reinterpret_cast<float2*>(base + e * 64)[lane] =
                make_float2(fmaf(dt, al, z0[e]), fmaf(dt, ah, z1[e]));
        }
        __syncwarp();
        mlp4(k3l, k3h);

#pragma unroll
        for (int e = 0; e < NB; e++) {
            float al = fmaf(A42, k2l[e], A41 * k1l[e]); al = fmaf(A43, k3l[e], al);
            float ah = fmaf(A42, k2h[e], A41 * k1h[e]); ah = fmaf(A43, k3h[e], ah);
            reinterpret_cast<float2*>(base + e * 64)[lane] =
                make_float2(fmaf(dt, al, z0[e]), fmaf(dt, ah, z1[e]));
        }
        __syncwarp();
        mlp4(k4l, k4h);

#pragma unroll
        for (int e = 0; e < NB; e++) {
            float al = fmaf(A52, k2l[e], A51 * k1l[e]);
            al = fmaf(A53, k3l[e], al); al = fmaf(A54, k4l[e], al);
            float ah = fmaf(A52, k2h[e], A51 * k1h[e]);
            ah = fmaf(A53, k3h[e], ah); ah = fmaf(A54, k4h[e], ah);
            reinterpret_cast<float2*>(base + e * 64)[lane] =
                make_float2(fmaf(dt, al, z0[e]), fmaf(dt, ah, z1[e]));
        }
        __syncwarp();
        mlp4(k5l, k5h);

#pragma unroll
        for (int e = 0; e < NB; e++) {
            float al = fmaf(A62, k2l[e], A61 * k1l[e]); al = fmaf(A63, k3l[e], al);
            al = fmaf(A64, k4l[e], al); al = fmaf(A65, k5l[e], al);
            float ah = fmaf(A62, k2h[e], A61 * k1h[e]); ah = fmaf(A63, k3h[e], ah);
            ah = fmaf(A64, k4h[e], ah); ah = fmaf(A65, k5h[e], ah);
            reinterpret_cast<float2*>(base + e * 64)[lane] =
                make_float2(fmaf(dt, al, z0[e]), fmaf(dt, ah, z1[e]));
        }
        __syncwarp();
        mlp4(k6l, k6h);

#pragma unroll
        for (int e = 0; e < NB; e++) {
            float s;
            s = B1c * k1l[e]; s = fmaf(B2c, k2l[e], s); s = fmaf(B3c, k3l[e], s);
            s = fmaf(B4c, k4l[e], s); s = fmaf(B5c, k5l[e], s); s = fmaf(B6c, k6l[e], s);
            z0[e] = fmaf(dt, s, z0[e]);
            s = B1c * k1h[e]; s = fmaf(B2c, k2h[e], s); s = fmaf(B3c, k3h[e], s);
            s = fmaf(B4c, k4h[e], s); s = fmaf(B5c, k5h[e], s); s = fmaf(B6c, k6h[e], s);
            z1[e] = fmaf(dt, s, z1[e]);
        }
    }
#pragma unroll
    for (int e = 0; e < NB; e++)
        reinterpret_cast<float2*>(zs + ((size_t)(b0 + e) * kT + NSTEPS) * kH)[lane] =
            make_float2(z0[e], z1[e]);
}

// ---- decode: ys = zs @ decW^T + decb, smem-staged tiles (unchanged R3) ----
constexpr int DEC_THREADS = 128;
constexpr int DEC_TILE = 16;
constexpr int DEC_GRID = 444;

__global__ void __launch_bounds__(DEC_THREADS)
dec_kernel(const float* __restrict__ zs, const float* __restrict__ decW,
           const float* __restrict__ decb, float* __restrict__ ys)
{
    __shared__ __align__(16) float sz[DEC_TILE * 64];
    const int tid = threadIdx.x;
    const int lane = tid & 31;
    const int wid = tid >> 5;

    u64 wa[32], wb[32];
    {
        const ulonglong2* va = reinterpret_cast<const ulonglong2*>(decW + (2*lane) * 64);
        const ulonglong2* vb = reinterpret_cast<const ulonglong2*>(decW + (2*lane+1) * 64);
#pragma unroll
        for (int i = 0; i < 16; i++) {
            ulonglong2 x = va[i], y = vb[i];
            wa[2*i] = x.x; wa[2*i+1] = x.y;
            wb[2*i] = y.x; wb[2*i+1] = y.y;
        }
    }
    const float2 db = *reinterpret_cast<const float2*>(decb + 2 * lane);

    const int nTiles = (kB * kT) / DEC_TILE;
#pragma unroll 1
    for (int tile = blockIdx.x; tile < nTiles; tile += DEC_GRID) {
        const float4* g = reinterpret_cast<const float4*>(zs + (size_t)tile * DEC_TILE * 64);
        float4* s4 = reinterpret_cast<float4*>(sz);
        s4[tid] = g[tid];
        s4[tid + 128] = g[tid + 128];
        __syncthreads();

        const int r0 = wid * 4;
#pragma unroll
        for (int rr = 0; rr < 4; rr++) {
            const ulonglong2* zr = reinterpret_cast<const ulonglong2*>(sz + (r0 + rr) * 64);
            u64 a0 = pk(db.x, 0.f), a1 = 0, c0 = pk(db.y, 0.f), c1 = 0;
#pragma unroll
            for (int kc = 0; kc < 16; kc++) {
                ulonglong2 v = zr[kc];
                a0 = fma2(v.x, wa[2*kc], a0); a1 = fma2(v.y, wa[2*kc+1], a1);
                c0 = fma2(v.x, wb[2*kc], c0); c1 = fma2(v.y, wb[2*kc+1], c1);
            }
            const size_t row = (size_t)tile * DEC_TILE + r0 + rr;
            reinterpret_cast<float2*>(ys + row * 64)[lane] =
                make_float2(hsum2(a0, a1), hsum2(c0, c1));
        }
        __syncthreads();
    }
}

} // namespace

extern "C" void kernel_launch(void* const* d_in, const int* in_sizes, int n_in,
                              void* d_out, int out_size) {
    const float* ts   = (const float*)d_in[0];
    const float* y0   = (const float*)d_in[1];
    const float* encW = (const float*)d_in[2];
    const float* encb = (const float*)d_in[3];
    const float* W1   = (const float*)d_in[4];
    const float* b1   = (const float*)d_in[5];
    const float* W2   = (const float*)d_in[6];
    const float* b2   = (const float*)d_in[7];
    const float* W3   = (const float*)d_in[8];
    const float* b3   = (const float*)d_in[9];
    const float* decW = (const float*)d_in[10];
    const float* decb = (const float*)d_in[11];

    float* ys = (float*)d_out;
    float* zs = ys + (size_t)out_size / 2;     // [ys | zs]

    ode_kernel<<<GRID, THREADS>>>(ts, y0, encW, encb, W1, b1, W2, b2, W3, b3, zs);
    dec_kernel<<<DEC_GRID, DEC_THREADS>>>(zs, decW, decb, ys);
}